// round 17
// baseline (speedup 1.0000x reference)
#include <cuda_runtime.h>
#include <cuda_fp16.h>
#include <cstdint>

// Shapes: B=4, H=W=64 -> N=4096 tokens per batch, C=256, FQ=32.
#define BATCH 4
#define NTOK 4096
#define CDIM 256
#define FQ 32
#define ROWS_TOTAL (BATCH * NTOK)   // 16384

// Scratch (no allocations allowed -> __device__ globals)
__device__ half g_qh[ROWS_TOTAL * FQ];     // [row][32] fp16
__device__ half g_kh[ROWS_TOTAL * FQ];     // [row][32] fp16
__device__ half g_vh[ROWS_TOTAL * CDIM];   // TRANSPOSED: [b][c][n] fp16
__device__ half g_atth[ROWS_TOTAL * CDIM]; // attended, fp16

// Pre-transposed fp16 weights: [col][k]
__device__ half g_wqkT[64 * 256];    // cols 0-31 = Wq, 32-63 = Wk
__device__ half g_wvT[256 * 256];
__device__ half g_woT[256 * 256];

__device__ __forceinline__ float relu(float v) { return v > 0.0f ? v : 0.0f; }

__device__ __forceinline__ uint32_t pack2(float a, float b) {
    half2 h = __floats2half2_rn(a, b);   // a -> .x (lower k)
    return *(uint32_t*)&h;
}

// ---------------------------------------------------------------------------
// Kernel 0: weight prep — fp32 [k][c] -> fp16 transposed [c][k].
// ---------------------------------------------------------------------------
__global__ __launch_bounds__(256) void prep_kernel(
    const float* __restrict__ Wq, const float* __restrict__ Wk,
    const float* __restrict__ Wv, const float* __restrict__ Wo)
{
    int i = blockIdx.x * 256 + threadIdx.x;   // 65536 total
    int k = i >> 8, c = i & 255;
    g_wvT[c * 256 + k] = __float2half(Wv[k * 256 + c]);
    g_woT[c * 256 + k] = __float2half(Wo[k * 256 + c]);
    if (i < 8192) {
        int kk = i >> 5, cc = i & 31;
        g_wqkT[cc * 256 + kk]        = __float2half(Wq[kk * 32 + cc]);
        g_wqkT[(cc + 32) * 256 + kk] = __float2half(Wk[kk * 32 + cc]);
    }
}

#define PROJ_SMEM_BYTES (2 * 64 * 264 * 2)

// ---------------------------------------------------------------------------
// Kernel 1: fused QKV projection, fp16 mma (fp32 accum). One CTA per 64-row
// tile: X staged ONCE, 5 weight tiles cycled through one smem buffer.
// ---------------------------------------------------------------------------
__global__ __launch_bounds__(256, 2) void qkv_kernel(
    const float* __restrict__ x,
    const float* __restrict__ bq, const float* __restrict__ bk,
    const float* __restrict__ bv)
{
    extern __shared__ char smraw[];
    half* Xs  = (half*)smraw;             // [64 r][264]
    half* Wsm = (half*)smraw + 64 * 264;  // [64 c][264]

    const int tid = threadIdx.x;
    const int lane = tid & 31, warp = tid >> 5;
    const int gID = lane >> 2, tig = lane & 3;
    const int row0 = blockIdx.x * 64;
    const int wr = (warp & 3) * 16;
    const int wc = (warp >> 2) * 32;

    // Stage X tile once (fp32 -> fp16)
#pragma unroll
    for (int it = 0; it < 16; ++it) {
        int fi = tid + it * 256;
        int r = fi >> 6, q = fi & 63;
        float4 v = *(const float4*)(x + (size_t)(row0 + r) * CDIM + q * 4);
        uint2 t = make_uint2(pack2(v.x, v.y), pack2(v.z, v.w));
        *(uint2*)(Xs + r * 264 + q * 4) = t;
    }

    for (int ct = 0; ct < 5; ++ct) {
        const half* wsrc = (ct == 0) ? g_wqkT : (g_wvT + (size_t)(ct - 1) * 64 * 256);
#pragma unroll
        for (int it = 0; it < 8; ++it) {
            int fi = tid + it * 256;
            int c = fi >> 5, q = fi & 31;
            uint4 t = *(const uint4*)(wsrc + (size_t)c * 256 + q * 8);
            *(uint4*)(Wsm + c * 264 + q * 8) = t;
        }
        __syncthreads();   // W ready (covers X stage for ct=0)

        float acc[16];
#pragma unroll
        for (int i = 0; i < 16; ++i) acc[i] = 0.0f;

#pragma unroll
        for (int ks = 0; ks < 16; ++ks) {
            const int d0 = ks * 16;
            uint32_t a0 = *(const uint32_t*)(Xs + (wr + gID) * 264 + d0 + 2 * tig);
            uint32_t a1 = *(const uint32_t*)(Xs + (wr + gID + 8) * 264 + d0 + 2 * tig);
            uint32_t a2 = *(const uint32_t*)(Xs + (wr + gID) * 264 + d0 + 2 * tig + 8);
            uint32_t a3 = *(const uint32_t*)(Xs + (wr + gID + 8) * 264 + d0 + 2 * tig + 8);
#pragma unroll
            for (int nt = 0; nt < 4; ++nt) {
                int n = wc + nt * 8 + gID;
                uint32_t b0 = *(const uint32_t*)(Wsm + n * 264 + d0 + 2 * tig);
                uint32_t b1 = *(const uint32_t*)(Wsm + n * 264 + d0 + 2 * tig + 8);
                float* o = acc + nt * 4;
                asm volatile(
                    "mma.sync.aligned.m16n8k16.row.col.f32.f16.f16.f32 "
                    "{%0,%1,%2,%3}, {%4,%5,%6,%7}, {%8,%9}, {%0,%1,%2,%3};"
                    : "+f"(o[0]), "+f"(o[1]), "+f"(o[2]), "+f"(o[3])
                    : "r"(a0), "r"(a1), "r"(a2), "r"(a3), "r"(b0), "r"(b1));
            }
        }
        __syncthreads();   // done reading Wsm; next stage may overwrite

        if (ct == 0) {
            int r0g = row0 + wr + gID, r1g = r0g + 8;
#pragma unroll
            for (int nt = 0; nt < 4; ++nt) {
                float* o = acc + nt * 4;
                int c = wc + nt * 8 + 2 * tig;
                if (c < 32) {
                    *(uint32_t*)(g_qh + (size_t)r0g * FQ + c) =
                        pack2(relu(o[0] + bq[c]), relu(o[1] + bq[c + 1]));
                    *(uint32_t*)(g_qh + (size_t)r1g * FQ + c) =
                        pack2(relu(o[2] + bq[c]), relu(o[3] + bq[c + 1]));
                } else {
                    int ck = c - 32;
                    *(uint32_t*)(g_kh + (size_t)r0g * FQ + ck) =
                        pack2(relu(o[0] + bk[ck]), relu(o[1] + bk[ck + 1]));
                    *(uint32_t*)(g_kh + (size_t)r1g * FQ + ck) =
                        pack2(relu(o[2] + bk[ck]), relu(o[3] + bk[ck + 1]));
                }
            }
        } else {
            const int bq_ = row0 >> 12;
            const int n0 = (row0 & 4095) + wr + gID;
#pragma unroll
            for (int nt = 0; nt < 4; ++nt) {
                float* o = acc + nt * 4;
                int cc = (ct - 1) * 64 + wc + nt * 8 + 2 * tig;
                float b0v = bv[cc], b1v = bv[cc + 1];
                half* base0 = g_vh + ((size_t)bq_ * CDIM + cc) * NTOK;
                half* base1 = base0 + NTOK;
                base0[n0]     = __float2half(relu(o[0] + b0v));
                base1[n0]     = __float2half(relu(o[1] + b1v));
                base0[n0 + 8] = __float2half(relu(o[2] + b0v));
                base1[n0 + 8] = __float2half(relu(o[3] + b1v));
            }
        }
    }
}

// ---------------------------------------------------------------------------
// Kernel 2: flash attention, fp16 HMMA (m16n8k16, fp32 accum), fp16 I/O.
// Deferred-l softmax: per-warp half-row sums live in registers (rescaled by
// the shared alpha each tile), running max double-buffered in smem.
// ---------------------------------------------------------------------------
#define H_QS 0
#define H_KS (H_QS + 64 * 40)
#define H_VT (H_KS + 64 * 40)
#define H_PS (H_VT + 256 * 72)
#define H_END (H_PS + 64 * 72)          // halves
#define F_STATS_OFF (H_END * 2)          // bytes
#define ATTN_SMEM_BYTES (F_STATS_OFF + 448 * 4)

__global__ __launch_bounds__(256, 2) void attn_kernel()
{
    extern __shared__ char smraw[];
    half* Qs = (half*)smraw + H_QS;
    half* Ks = (half*)smraw + H_KS;
    half* Vt = (half*)smraw + H_VT;
    half* Ps = (half*)smraw + H_PS;
    float* mbuf = (float*)(smraw + F_STATS_OFF);  // [2][64] running max
    float* aS   = mbuf + 128;                     // [64] alpha
    float* pmx  = aS + 64;                        // [2][64] partial max
    float* psm  = pmx + 128;                      // [2][64] final partial sums

    const int tid = threadIdx.x;
    const int b = blockIdx.y;
    const int q0 = blockIdx.x * 64;
    const int lane = tid & 31, warp = tid >> 5;
    const int gID = lane >> 2, tig = lane & 3;
    const int srow0 = (warp & 3) * 16;
    const int scol0 = (warp >> 2) * 32;
    const int shalf = warp >> 2;
    const int wr = (warp & 1) * 32;
    const int wc = (warp >> 1) * 64;

    const half* qh = g_qh + (size_t)b * NTOK * FQ;
    const half* kh = g_kh + (size_t)b * NTOK * FQ;
    const half* vh = g_vh + (size_t)b * CDIM * NTOK;   // [c][n]

    // Stage Q
    {
        int r = tid >> 2, qo = tid & 3;
        uint4 v = *(const uint4*)(qh + (size_t)(q0 + r) * FQ + qo * 8);
        *(uint4*)(Qs + r * 40 + qo * 8) = v;
    }
    if (tid < 64) mbuf[tid] = -1e30f;   // buffer 0 (read at kt=0)

    float O[64];
#pragma unroll
    for (int i = 0; i < 64; ++i) O[i] = 0.0f;
    float lr0 = 0.0f, lr1 = 0.0f;       // per-warp half-row running sums
    const int r0 = srow0 + gID, r1 = r0 + 8;

    for (int kt = 0; kt < 64; ++kt) {
        const int k0 = kt * 64;
        __syncthreads();   // Ks/Vt free (prev PV done)

        {
            int j = tid >> 2, qo = tid & 3;
            uint4 v = *(const uint4*)(kh + (size_t)(k0 + j) * FQ + qo * 8);
            *(uint4*)(Ks + j * 40 + qo * 8) = v;
        }
#pragma unroll
        for (int it = 0; it < 8; ++it) {
            int fi = tid + it * 256;
            int c = fi >> 3, q = fi & 7;
            uint4 v = *(const uint4*)(vh + (size_t)c * NTOK + k0 + q * 8);
            *(uint4*)(Vt + c * 72 + q * 8) = v;
        }
        __syncthreads();

        // ---- S = Q K^T. Warp strip 16x32. ----
        float c[16];
#pragma unroll
        for (int i = 0; i < 16; ++i) c[i] = 0.0f;
#pragma unroll
        for (int kks = 0; kks < 2; ++kks) {
            const int d0 = kks * 16;
            uint32_t a0 = *(const uint32_t*)(Qs + (srow0 + gID) * 40 + d0 + 2 * tig);
            uint32_t a1 = *(const uint32_t*)(Qs + (srow0 + gID + 8) * 40 + d0 + 2 * tig);
            uint32_t a2 = *(const uint32_t*)(Qs + (srow0 + gID) * 40 + d0 + 2 * tig + 8);
            uint32_t a3 = *(const uint32_t*)(Qs + (srow0 + gID + 8) * 40 + d0 + 2 * tig + 8);
#pragma unroll
            for (int nt = 0; nt < 4; ++nt) {
                int n = scol0 + nt * 8 + gID;
                uint32_t b0 = *(const uint32_t*)(Ks + n * 40 + d0 + 2 * tig);
                uint32_t b1 = *(const uint32_t*)(Ks + n * 40 + d0 + 2 * tig + 8);
                float* o = c + nt * 4;
                asm volatile(
                    "mma.sync.aligned.m16n8k16.row.col.f32.f16.f16.f32 "
                    "{%0,%1,%2,%3}, {%4,%5,%6,%7}, {%8,%9}, {%0,%1,%2,%3};"
                    : "+f"(o[0]), "+f"(o[1]), "+f"(o[2]), "+f"(o[3])
                    : "r"(a0), "r"(a1), "r"(a2), "r"(a3), "r"(b0), "r"(b1));
            }
        }

        // ---- softmax (deferred l, double-buffered max) ----
        float m0 = -1e30f, m1 = -1e30f;
#pragma unroll
        for (int nt = 0; nt < 4; ++nt) {
            m0 = fmaxf(m0, fmaxf(c[nt * 4 + 0], c[nt * 4 + 1]));
            m1 = fmaxf(m1, fmaxf(c[nt * 4 + 2], c[nt * 4 + 3]));
        }
        m0 = fmaxf(m0, __shfl_xor_sync(0xffffffffu, m0, 1));
        m0 = fmaxf(m0, __shfl_xor_sync(0xffffffffu, m0, 2));
        m1 = fmaxf(m1, __shfl_xor_sync(0xffffffffu, m1, 1));
        m1 = fmaxf(m1, __shfl_xor_sync(0xffffffffu, m1, 2));
        if (tig == 0) {
            pmx[shalf * 64 + r0] = m0;
            pmx[shalf * 64 + r1] = m1;
        }
        __syncthreads();

        const int par = kt & 1;
        float mold0 = mbuf[par * 64 + r0];
        float mold1 = mbuf[par * 64 + r1];
        float mn0 = fmaxf(mold0, fmaxf(pmx[r0], pmx[64 + r0]));
        float mn1 = fmaxf(mold1, fmaxf(pmx[r1], pmx[64 + r1]));
        float s0 = 0.0f, s1 = 0.0f;
#pragma unroll
        for (int nt = 0; nt < 4; ++nt) {
            int coln = scol0 + nt * 8 + 2 * tig;
            float p0 = __expf(c[nt * 4 + 0] - mn0);
            float p1 = __expf(c[nt * 4 + 1] - mn0);
            float p2 = __expf(c[nt * 4 + 2] - mn1);
            float p3 = __expf(c[nt * 4 + 3] - mn1);
            s0 += p0 + p1;
            s1 += p2 + p3;
            *(uint32_t*)(Ps + r0 * 72 + coln) = pack2(p0, p1);
            *(uint32_t*)(Ps + r1 * 72 + coln) = pack2(p2, p3);
        }
        s0 += __shfl_xor_sync(0xffffffffu, s0, 1);
        s0 += __shfl_xor_sync(0xffffffffu, s0, 2);
        s1 += __shfl_xor_sync(0xffffffffu, s1, 1);
        s1 += __shfl_xor_sync(0xffffffffu, s1, 2);
        float a0f = __expf(mold0 - mn0);
        float a1f = __expf(mold1 - mn1);
        lr0 = lr0 * a0f + s0;
        lr1 = lr1 * a1f + s1;
        if (shalf == 0 && tig == 0) {
            mbuf[(par ^ 1) * 64 + r0] = mn0;
            mbuf[(par ^ 1) * 64 + r1] = mn1;
            aS[r0] = a0f;
            aS[r1] = a1f;
        }
        __syncthreads();   // P + aS ready

        // ---- O = O*alpha + P V ----
        float al[4];
        al[0] = aS[wr + gID];
        al[1] = aS[wr + gID + 8];
        al[2] = aS[wr + 16 + gID];
        al[3] = aS[wr + 24 + gID];
#pragma unroll
        for (int mt = 0; mt < 2; ++mt)
#pragma unroll
            for (int nt = 0; nt < 8; ++nt) {
                float* o = O + (mt * 8 + nt) * 4;
                o[0] *= al[mt * 2]; o[1] *= al[mt * 2];
                o[2] *= al[mt * 2 + 1]; o[3] *= al[mt * 2 + 1];
            }

#pragma unroll
        for (int kk = 0; kk < 4; ++kk) {
            const int j0 = kk * 16;
            uint32_t A[2][4];
#pragma unroll
            for (int mt = 0; mt < 2; ++mt) {
                int rr = wr + mt * 16 + gID;
                A[mt][0] = *(const uint32_t*)(Ps + rr * 72 + j0 + 2 * tig);
                A[mt][1] = *(const uint32_t*)(Ps + (rr + 8) * 72 + j0 + 2 * tig);
                A[mt][2] = *(const uint32_t*)(Ps + rr * 72 + j0 + 2 * tig + 8);
                A[mt][3] = *(const uint32_t*)(Ps + (rr + 8) * 72 + j0 + 2 * tig + 8);
            }
#pragma unroll
            for (int nt = 0; nt < 8; ++nt) {
                int n = wc + nt * 8 + gID;
                uint32_t B0 = *(const uint32_t*)(Vt + n * 72 + j0 + 2 * tig);
                uint32_t B1 = *(const uint32_t*)(Vt + n * 72 + j0 + 2 * tig + 8);
#pragma unroll
                for (int mt = 0; mt < 2; ++mt) {
                    float* o = O + (mt * 8 + nt) * 4;
                    asm volatile(
                        "mma.sync.aligned.m16n8k16.row.col.f32.f16.f16.f32 "
                        "{%0,%1,%2,%3}, {%4,%5,%6,%7}, {%8,%9}, {%0,%1,%2,%3};"
                        : "+f"(o[0]), "+f"(o[1]), "+f"(o[2]), "+f"(o[3])
                        : "r"(A[mt][0]), "r"(A[mt][1]), "r"(A[mt][2]), "r"(A[mt][3]),
                          "r"(B0), "r"(B1));
                }
            }
        }
    }

    // publish final partial sums, combine, write attended (fp16)
    if (tig == 0) {
        psm[shalf * 64 + r0] = lr0;
        psm[shalf * 64 + r1] = lr1;
    }
    __syncthreads();

#pragma unroll
    for (int mt = 0; mt < 2; ++mt) {
        int r0o = wr + mt * 16 + gID;
        int r1o = r0o + 8;
        float inv0 = 1.0f / (psm[r0o] + psm[64 + r0o]);
        float inv1 = 1.0f / (psm[r1o] + psm[64 + r1o]);
        half* d0 = g_atth + ((size_t)b * NTOK + q0 + r0o) * CDIM;
        half* d1 = g_atth + ((size_t)b * NTOK + q0 + r1o) * CDIM;
#pragma unroll
        for (int nt = 0; nt < 8; ++nt) {
            float* o = O + (mt * 8 + nt) * 4;
            int cc = wc + nt * 8 + tig * 2;
            *(uint32_t*)(d0 + cc) = pack2(o[0] * inv0, o[1] * inv0);
            *(uint32_t*)(d1 + cc) = pack2(o[2] * inv1, o[3] * inv1);
        }
    }
}

// ---------------------------------------------------------------------------
// Kernel 3: output projection + ReLU + residual. One CTA per 64-row tile,
// attended staged once, 4 Wo tiles cycled.
// ---------------------------------------------------------------------------
__global__ __launch_bounds__(256, 2) void out_kernel(
    const float* __restrict__ x,
    const float* __restrict__ bo,
    float* __restrict__ out)
{
    extern __shared__ char smraw[];
    half* Xs  = (half*)smraw;
    half* Wsm = (half*)smraw + 64 * 264;

    const int tid = threadIdx.x;
    const int lane = tid & 31, warp = tid >> 5;
    const int gID = lane >> 2, tig = lane & 3;
    const int row0 = blockIdx.x * 64;
    const int wr = (warp & 3) * 16;
    const int wc = (warp >> 2) * 32;

    // Stage attended once (already fp16)
#pragma unroll
    for (int it = 0; it < 8; ++it) {
        int fi = tid + it * 256;
        int r = fi >> 5, q = fi & 31;
        uint4 v = *(const uint4*)(g_atth + (size_t)(row0 + r) * CDIM + q * 8);
        *(uint4*)(Xs + r * 264 + q * 8) = v;
    }

    for (int ct = 0; ct < 4; ++ct) {
        const half* wsrc = g_woT + (size_t)ct * 64 * 256;
#pragma unroll
        for (int it = 0; it < 8; ++it) {
            int fi = tid + it * 256;
            int c = fi >> 5, q = fi & 31;
            uint4 t = *(const uint4*)(wsrc + (size_t)c * 256 + q * 8);
            *(uint4*)(Wsm + c * 264 + q * 8) = t;
        }
        __syncthreads();

        float acc[16];
#pragma unroll
        for (int i = 0; i < 16; ++i) acc[i] = 0.0f;

#pragma unroll
        for (int ks = 0; ks < 16; ++ks) {
            const int d0 = ks * 16;
            uint32_t a0 = *(const uint32_t*)(Xs + (wr + gID) * 264 + d0 + 2 * tig);
            uint32_t a1 = *(const uint32_t*)(Xs + (wr + gID + 8) * 264 + d0 + 2 * tig);
            uint32_t a2 = *(const uint32_t*)(Xs + (wr + gID) * 264 + d0 + 2 * tig + 8);
            uint32_t a3 = *(const uint32_t*)(Xs + (wr + gID + 8) * 264 + d0 + 2 * tig + 8);
#pragma unroll
            for (int nt = 0; nt < 4; ++nt) {
                int n = wc + nt * 8 + gID;
                uint32_t b0 = *(const uint32_t*)(Wsm + n * 264 + d0 + 2 * tig);
                uint32_t b1 = *(const uint32_t*)(Wsm + n * 264 + d0 + 2 * tig + 8);
                float* o = acc + nt * 4;
                asm volatile(
                    "mma.sync.aligned.m16n8k16.row.col.f32.f16.f16.f32 "
                    "{%0,%1,%2,%3}, {%4,%5,%6,%7}, {%8,%9}, {%0,%1,%2,%3};"
                    : "+f"(o[0]), "+f"(o[1]), "+f"(o[2]), "+f"(o[3])
                    : "r"(a0), "r"(a1), "r"(a2), "r"(a3), "r"(b0), "r"(b1));
            }
        }
        __syncthreads();

        int r0g = row0 + wr + gID, r1g = r0g + 8;
#pragma unroll
        for (int nt = 0; nt < 4; ++nt) {
            float* o = acc + nt * 4;
            int cc = ct * 64 + wc + nt * 8 + 2 * tig;
            float b0v = bo[cc], b1v = bo[cc + 1];
            float2 x0 = *(const float2*)(x + (size_t)r0g * CDIM + cc);
            float2 x1 = *(const float2*)(x + (size_t)r1g * CDIM + cc);
            float2 v0 = make_float2(x0.x + relu(o[0] + b0v), x0.y + relu(o[1] + b1v));
            float2 v1 = make_float2(x1.x + relu(o[2] + b0v), x1.y + relu(o[3] + b1v));
            *(float2*)(out + (size_t)r0g * CDIM + cc) = v0;
            *(float2*)(out + (size_t)r1g * CDIM + cc) = v1;
        }
    }
}

// ---------------------------------------------------------------------------
extern "C" void kernel_launch(void* const* d_in, const int* in_sizes, int n_in,
                              void* d_out, int out_size)
{
    const float* x  = (const float*)d_in[0];
    const float* Wq = (const float*)d_in[1];
    const float* bq = (const float*)d_in[2];
    const float* Wk = (const float*)d_in[3];
    const float* bk = (const float*)d_in[4];
    const float* Wv = (const float*)d_in[5];
    const float* bv = (const float*)d_in[6];
    const float* Wo = (const float*)d_in[7];
    const float* bo = (const float*)d_in[8];
    float* out = (float*)d_out;

    cudaFuncSetAttribute(attn_kernel, cudaFuncAttributeMaxDynamicSharedMemorySize,
                         ATTN_SMEM_BYTES);
    cudaFuncSetAttribute(qkv_kernel, cudaFuncAttributeMaxDynamicSharedMemorySize,
                         PROJ_SMEM_BYTES);
    cudaFuncSetAttribute(out_kernel, cudaFuncAttributeMaxDynamicSharedMemorySize,
                         PROJ_SMEM_BYTES);

    prep_kernel<<<256, 256>>>(Wq, Wk, Wv, Wo);
    qkv_kernel<<<256, 256, PROJ_SMEM_BYTES>>>(x, bq, bk, bv);
    attn_kernel<<<dim3(64, 4), 256, ATTN_SMEM_BYTES>>>();
    out_kernel<<<256, 256, PROJ_SMEM_BYTES>>>(x, bo, out);
}